// round 1
// baseline (speedup 1.0000x reference)
#include <cuda_runtime.h>
#include <cuda_bf16.h>
#include <math.h>

// Problem constants
#define Bc 128
#define Nc 128
#define Ec 64
#define TYPEC 201   // TYPE_NUM+1
#define RELC  51    // REL_NUM+1

// Precomputed batch-independent tables
__device__ float g_typeproj[TYPEC * 192];   // [tv][gate*64+e] = bg[e] + type_table[tv]@Wg[0:32]
__device__ float g_relproj[RELC * 64];      // [v][e]          = rel_table[v]@W_in[64:96]

struct GParams {
    const int*   node_slice;
    const int*   type_slice;
    const float* distance;
    const int*   rel_matrix;
    const int*   input_length;
    const float* emb_table;
    const float* type_table;
    const float* rel_table;
    const float* W_in; const float* b_in;
    const float* Wr;   const float* br;
    const float* Wz;   const float* bz;
    const float* Wt;   const float* bt;
    const float* W_co; const float* b_co;
    const float* W1;   const float* b1;
    const float* W2;   const float* b2;
    const float* W3;   const float* b3;
    const float* W4;   const float* b4;
    float* out;
};

// ---------------------------------------------------------------------------
// Kernel 0: batch-independent projection tables (tiny)
// ---------------------------------------------------------------------------
__global__ void ggnn_pre(GParams p) {
    int blk = blockIdx.x;
    int t = threadIdx.x;
    if (blk < TYPEC) {
        if (t < 192) {
            int gate = t >> 6, e = t & 63;
            const float* Wg = (gate == 0) ? p.Wr : ((gate == 1) ? p.Wz : p.Wt);
            const float* bg = (gate == 0) ? p.br : ((gate == 1) ? p.bz : p.bt);
            float acc = bg[e];
            #pragma unroll
            for (int k = 0; k < 32; k++)
                acc += p.type_table[blk * 32 + k] * Wg[k * 64 + e];
            g_typeproj[blk * 192 + t] = acc;
        }
    } else {
        if (t < 64) {
            for (int v = 0; v < RELC; v++) {
                float acc = 0.f;
                #pragma unroll
                for (int k = 0; k < 32; k++)
                    acc += p.rel_table[v * 32 + k] * p.W_in[(64 + k) * 64 + t];
                g_relproj[v * 64 + t] = acc;
            }
        }
    }
}

// ---------------------------------------------------------------------------
// Main kernel: one CTA per batch element, 512 threads, ~213 KB dynamic smem.
// Shared layout (float offsets):
//   H        @     0  (8192)  : hidden@W_h + b_in, incrementally updated
//   HID      @  8192  (8192)  : hidden state
//   NP       @ 16384 (24576)  : now_part[i][gate*64+e] (static per-step gate input)
//   RP       @ 40960  (3264)  : relproj copy
//   DISC     @ 44224   (128)
//   PART     @ 44352   (512)  : max partials (8 groups x 64)
//   DP       @ 44864    (64)  : dis_pre
//   Rg       @ 44928    (64)
//   Zg       @ 44992    (64)
//   HHg      @ 45056    (64)
//   NR       @ 45120    (64)
//   BIN      @ 45184    (64)
//   RV       @ 45248   (256)  : int, 2x128 double-buffered rel rows
//   TV       @ 45504   (128)  : int, type row
//   FIN      @ 45632   (736)  : final head scratch
//   STAGE    @ 46368  (8192)  : init GEMM weight staging
// ---------------------------------------------------------------------------
#define SM_H     0
#define SM_HID   8192
#define SM_NP    16384
#define SM_RP    40960
#define SM_DISC  44224
#define SM_PART  44352
#define SM_DP    44864
#define SM_R     44928
#define SM_Z     44992
#define SM_HH    45056
#define SM_NR    45120
#define SM_BIN   45184
#define SM_RV    45248
#define SM_TV    45504
#define SM_FIN   45632
#define SM_STAGE 46368
#define SMEM_FLOATS 54560

__global__ void __launch_bounds__(512, 1) ggnn_main(GParams p) {
    extern __shared__ float S[];
    const int t = threadIdx.x;
    const int b = blockIdx.x;
    int* rvs = (int*)&S[SM_RV];
    int* tvs = (int*)&S[SM_TV];
    const int len = p.input_length[b];

    // ---------------- init gathers ----------------
    {
        const float4* emb4 = (const float4*)p.emb_table;
        float4* hid4 = (float4*)&S[SM_HID];
        for (int idx = t; idx < Nc * 16; idx += 512) {
            int j = idx >> 4, q = idx & 15;
            long long nd = p.node_slice[b * Nc + j];
            hid4[idx] = emb4[nd * 16 + q];
        }
    }
    if (t < 128) S[SM_DISC + t] = -0.1f * p.distance[b * Nc + t];
    if (t < 128) tvs[t] = p.type_slice[b * Nc + t];
    if (t < 128) rvs[t] = p.rel_matrix[((long long)b * Nc) * Nc + t];
    for (int idx = t; idx < RELC * 64; idx += 512) S[SM_RP + idx] = g_relproj[idx];
    if (t < 64) S[SM_BIN + t] = p.b_in[t];

    // ---------------- persistent gate weights in registers ----------------
    // t in [0,256):  Wr/Wz dis_pre-part columns (2 threads per output, 32 regs)
    // t in [256,384): Wt dis_pre-part columns
    // t in [384,512): W_in hidden-part (W_h) columns
    float wreg[32];
    if (t < 256) {
        int ridx = t >> 1, half = t & 1;
        int gate = ridx >> 6, e = ridx & 63;
        const float* src = gate ? p.Wz : p.Wr;
        #pragma unroll
        for (int kk = 0; kk < 32; kk++) wreg[kk] = src[(96 + half * 32 + kk) * 64 + e];
    } else if (t < 384) {
        int u = t - 256, half = u & 1, e = u >> 1;
        #pragma unroll
        for (int kk = 0; kk < 32; kk++) wreg[kk] = p.Wt[(96 + half * 32 + kk) * 64 + e];
    } else {
        int u = t - 384, half = u & 1, e = u >> 1;
        #pragma unroll
        for (int kk = 0; kk < 32; kk++) wreg[kk] = p.W_in[(half * 32 + kk) * 64 + e];
    }
    __syncthreads();

    // ---------------- H init: H = hidden @ W_h + b_in ----------------
    for (int idx = t; idx < 4096; idx += 512) S[SM_STAGE + idx] = p.W_in[idx];
    __syncthreads();
    {
        int j0 = (t >> 4) << 2, e0 = (t & 15) << 2;
        float acc[4][4];
        #pragma unroll
        for (int m = 0; m < 4; m++)
            #pragma unroll
            for (int n = 0; n < 4; n++) acc[m][n] = S[SM_BIN + e0 + n];
        #pragma unroll 4
        for (int k = 0; k < 64; k++) {
            float4 w = *(const float4*)&S[SM_STAGE + k * 64 + e0];
            #pragma unroll
            for (int m = 0; m < 4; m++) {
                float h = S[SM_HID + (j0 + m) * 64 + k];
                acc[m][0] += h * w.x; acc[m][1] += h * w.y;
                acc[m][2] += h * w.z; acc[m][3] += h * w.w;
            }
        }
        #pragma unroll
        for (int m = 0; m < 4; m++)
            #pragma unroll
            for (int n = 0; n < 4; n++) S[SM_H + (j0 + m) * 64 + e0 + n] = acc[m][n];
    }
    __syncthreads();

    // ---------------- now_part: typeproj[tv] + node_emb @ Wg[32:96] ----------------
    // Pass A: gates r,z (128 output cols)
    for (int idx = t; idx < 8192; idx += 512) {
        int k = idx >> 7, c = idx & 127;
        S[SM_STAGE + idx] = (c < 64) ? p.Wr[(32 + k) * 64 + c]
                                     : p.Wz[(32 + k) * 64 + (c - 64)];
    }
    __syncthreads();
    #pragma unroll
    for (int pss = 0; pss < 2; pss++) {
        int tid2 = t + pss * 512;
        int i0 = (tid2 >> 5) << 2, c0 = (tid2 & 31) << 2;
        float acc[4][4];
        #pragma unroll
        for (int m = 0; m < 4; m++) {
            const float* tp = &g_typeproj[tvs[i0 + m] * 192 + c0];
            acc[m][0] = tp[0]; acc[m][1] = tp[1]; acc[m][2] = tp[2]; acc[m][3] = tp[3];
        }
        #pragma unroll 4
        for (int k = 0; k < 64; k++) {
            float4 w = *(const float4*)&S[SM_STAGE + k * 128 + c0];
            #pragma unroll
            for (int m = 0; m < 4; m++) {
                float h = S[SM_HID + (i0 + m) * 64 + k];
                acc[m][0] += h * w.x; acc[m][1] += h * w.y;
                acc[m][2] += h * w.z; acc[m][3] += h * w.w;
            }
        }
        #pragma unroll
        for (int m = 0; m < 4; m++)
            #pragma unroll
            for (int n = 0; n < 4; n++)
                S[SM_NP + (i0 + m) * 192 + c0 + n] = acc[m][n];
    }
    __syncthreads();
    // Pass B: gate t (64 output cols)
    for (int idx = t; idx < 4096; idx += 512) {
        int k = idx >> 6, e = idx & 63;
        S[SM_STAGE + idx] = p.Wt[(32 + k) * 64 + e];
    }
    __syncthreads();
    {
        int i0 = (t >> 4) << 2, e0 = (t & 15) << 2;
        float acc[4][4];
        #pragma unroll
        for (int m = 0; m < 4; m++) {
            const float* tp = &g_typeproj[tvs[i0 + m] * 192 + 128 + e0];
            acc[m][0] = tp[0]; acc[m][1] = tp[1]; acc[m][2] = tp[2]; acc[m][3] = tp[3];
        }
        #pragma unroll 4
        for (int k = 0; k < 64; k++) {
            float4 w = *(const float4*)&S[SM_STAGE + k * 64 + e0];
            #pragma unroll
            for (int m = 0; m < 4; m++) {
                float h = S[SM_HID + (i0 + m) * 64 + k];
                acc[m][0] += h * w.x; acc[m][1] += h * w.y;
                acc[m][2] += h * w.z; acc[m][3] += h * w.w;
            }
        }
        #pragma unroll
        for (int m = 0; m < 4; m++)
            #pragma unroll
            for (int n = 0; n < 4; n++)
                S[SM_NP + (i0 + m) * 192 + 128 + e0 + n] = acc[m][n];
    }
    __syncthreads();

    // ---------------- sequential scan over i ----------------
    const int tE = t & 63, tJG = t >> 6;
    for (int i = 0; i < Nc; i++) {
        const int* rv = rvs + (i & 1) * 128;
        // S0: masked max over j of relu(H[j]+relproj[rv[j]]) * disc[j]
        float acc = -1e30f;
        #pragma unroll
        for (int jj = 0; jj < 16; jj++) {
            int j = tJG + (jj << 3);
            int rvj = rv[j];
            float hv = S[SM_H + j * 64 + tE];
            float rp = S[SM_RP + rvj * 64 + tE];
            float c = fmaxf(hv + rp, 0.0f) * S[SM_DISC + j];
            bool valid = (rvj != 0) && (j < len);
            acc = fmaxf(acc, valid ? c : -1e30f);
        }
        S[SM_PART + tJG * 64 + tE] = acc;
        __syncthreads();
        // S1: reduce partials -> dis_pre; prefetch next rel row with idle warps
        if (t < 64) {
            float m = S[SM_PART + t];
            #pragma unroll
            for (int g = 1; g < 8; g++) m = fmaxf(m, S[SM_PART + g * 64 + t]);
            S[SM_DP + t] = (m < -1e29f) ? 0.0f : m;
        } else if (t >= 384) {
            if (i + 1 < Nc)
                rvs[((i + 1) & 1) * 128 + (t - 384)] =
                    p.rel_matrix[((long long)b * Nc + (i + 1)) * Nc + (t - 384)];
        }
        __syncthreads();
        // S2: r, z gates (2 threads per output, weights in regs)
        if (t < 256) {
            int ridx = t >> 1, half = t & 1;
            int gate = ridx >> 6, e = ridx & 63;
            int base = half * 32;
            float s0 = 0.f, s1 = 0.f, s2 = 0.f, s3 = 0.f;
            #pragma unroll
            for (int kk = 0; kk < 32; kk += 4) {
                s0 += wreg[kk]     * S[SM_DP + base + kk];
                s1 += wreg[kk + 1] * S[SM_DP + base + kk + 1];
                s2 += wreg[kk + 2] * S[SM_DP + base + kk + 2];
                s3 += wreg[kk + 3] * S[SM_DP + base + kk + 3];
            }
            float sum = (s0 + s1) + (s2 + s3);
            sum += __shfl_xor_sync(0xffffffffu, sum, 1);
            if (half == 0) {
                float v = S[SM_NP + i * 192 + gate * 64 + e] + sum;
                S[(gate ? SM_Z : SM_R) + e] = 1.0f / (1.0f + __expf(-v));
            }
        }
        __syncthreads();
        // S3: h_hat gate (input r*dis_pre)
        if (t >= 256 && t < 384) {
            int u = t - 256, half = u & 1, e = u >> 1;
            int base = half * 32;
            float s0 = 0.f, s1 = 0.f, s2 = 0.f, s3 = 0.f;
            #pragma unroll
            for (int kk = 0; kk < 32; kk += 4) {
                s0 += wreg[kk]     * (S[SM_R + base + kk]     * S[SM_DP + base + kk]);
                s1 += wreg[kk + 1] * (S[SM_R + base + kk + 1] * S[SM_DP + base + kk + 1]);
                s2 += wreg[kk + 2] * (S[SM_R + base + kk + 2] * S[SM_DP + base + kk + 2]);
                s3 += wreg[kk + 3] * (S[SM_R + base + kk + 3] * S[SM_DP + base + kk + 3]);
            }
            float sum = (s0 + s1) + (s2 + s3);
            sum += __shfl_xor_sync(0xffffffffu, sum, 1);
            if (half == 0)
                S[SM_HH + e] = tanhf(S[SM_NP + i * 192 + 128 + e] + sum);
        }
        __syncthreads();
        // S4: GRU update, new row
        if (t < 64) {
            float z = S[SM_Z + t], dp = S[SM_DP + t], hh = S[SM_HH + t];
            float up = (1.0f - z) * dp + z * hh;
            float nr = (i < len) ? up : S[SM_HID + i * 64 + t];
            S[SM_HID + i * 64 + t] = nr;
            S[SM_NR + t] = nr;
        }
        __syncthreads();
        // S5: incremental H row update: H[i] = b_in + new_row @ W_h
        if (t >= 384) {
            int u = t - 384, half = u & 1, e = u >> 1;
            int base = half * 32;
            float s0 = 0.f, s1 = 0.f, s2 = 0.f, s3 = 0.f;
            #pragma unroll
            for (int kk = 0; kk < 32; kk += 4) {
                s0 += wreg[kk]     * S[SM_NR + base + kk];
                s1 += wreg[kk + 1] * S[SM_NR + base + kk + 1];
                s2 += wreg[kk + 2] * S[SM_NR + base + kk + 2];
                s3 += wreg[kk + 3] * S[SM_NR + base + kk + 3];
            }
            float sum = (s0 + s1) + (s2 + s3);
            sum += __shfl_xor_sync(0xffffffffu, sum, 1);
            if (half == 0) S[SM_H + i * 64 + e] = S[SM_BIN + e] + sum;
        }
        __syncthreads();
    }

    // ---------------- final head ----------------
    {
        float acc = -1e30f;
        #pragma unroll
        for (int jj = 0; jj < 16; jj++) {
            int j = tJG + (jj << 3);
            if (j < len) acc = fmaxf(acc, S[SM_HID + j * 64 + tE]);
        }
        S[SM_PART + tJG * 64 + tE] = acc;
    }
    __syncthreads();
    if (t < 64) {
        float m = S[SM_PART + t];
        #pragma unroll
        for (int g = 1; g < 8; g++) m = fmaxf(m, S[SM_PART + g * 64 + t]);
        S[SM_FIN + 128 + t] = m;                             // sub
        S[SM_FIN + t]       = S[SM_HID + t];                 // user
        S[SM_FIN + 64 + t]  = S[SM_HID + (len - 1) * 64 + t]; // item
    }
    __syncthreads();
    if (t < 128) {  // ua / ia
        int which = t >> 6, e = t & 63;
        const float* first = which ? &S[SM_FIN + 64] : &S[SM_FIN];
        float acc = p.b_co[e];
        #pragma unroll 4
        for (int k = 0; k < 64; k++) acc += first[k] * p.W_co[k * 64 + e];
        #pragma unroll 4
        for (int k = 0; k < 64; k++) acc += S[SM_FIN + 128 + k] * p.W_co[(64 + k) * 64 + e];
        S[SM_FIN + 192 + which * 64 + e] = fmaxf(acc, 0.f);
    }
    __syncthreads();
    if (t < 192) {  // temp = [ua*user, sub, ia*item]
        float v;
        if (t < 64)       v = S[SM_FIN + 192 + t] * S[SM_FIN + t];
        else if (t < 128) v = S[SM_FIN + 128 + (t - 64)];
        else              v = S[SM_FIN + 256 + (t - 128)] * S[SM_FIN + 64 + (t - 128)];
        S[SM_FIN + 320 + t] = v;
    }
    __syncthreads();
    if (t < 128) {
        float acc = p.b1[t];
        #pragma unroll 4
        for (int k = 0; k < 192; k++) acc += S[SM_FIN + 320 + k] * p.W1[k * 128 + t];
        S[SM_FIN + 512 + t] = fmaxf(acc, 0.f);
    }
    __syncthreads();
    if (t < 64) {
        float acc = p.b2[t];
        #pragma unroll 4
        for (int k = 0; k < 128; k++) acc += S[SM_FIN + 512 + k] * p.W2[k * 64 + t];
        S[SM_FIN + 640 + t] = fmaxf(acc, 0.f);
    }
    __syncthreads();
    if (t < 32) {
        float acc = p.b3[t];
        #pragma unroll 4
        for (int k = 0; k < 64; k++) acc += S[SM_FIN + 640 + k] * p.W3[k * 32 + t];
        S[SM_FIN + 704 + t] = fmaxf(acc, 0.f);
    }
    __syncthreads();
    if (t == 0) {
        float acc = p.b4[0];
        #pragma unroll
        for (int k = 0; k < 32; k++) acc += S[SM_FIN + 704 + k] * p.W4[k];
        p.out[b] = 1.0f / (1.0f + __expf(-acc));
    }
}

// ---------------------------------------------------------------------------
extern "C" void kernel_launch(void* const* d_in, const int* in_sizes, int n_in,
                              void* d_out, int out_size) {
    GParams p;
    p.node_slice   = (const int*)d_in[0];
    p.type_slice   = (const int*)d_in[1];
    p.distance     = (const float*)d_in[2];
    p.rel_matrix   = (const int*)d_in[3];
    p.input_length = (const int*)d_in[4];
    // isBatch scalar may or may not appear as input index 5
    int o = (n_in >= 27) ? 6 : 5;
    p.emb_table  = (const float*)d_in[o + 0];
    p.type_table = (const float*)d_in[o + 1];
    p.rel_table  = (const float*)d_in[o + 2];
    p.W_in = (const float*)d_in[o + 3];  p.b_in = (const float*)d_in[o + 4];
    p.Wr   = (const float*)d_in[o + 5];  p.br   = (const float*)d_in[o + 6];
    p.Wz   = (const float*)d_in[o + 7];  p.bz   = (const float*)d_in[o + 8];
    p.Wt   = (const float*)d_in[o + 9];  p.bt   = (const float*)d_in[o + 10];
    p.W_co = (const float*)d_in[o + 11]; p.b_co = (const float*)d_in[o + 12];
    p.W1   = (const float*)d_in[o + 13]; p.b1   = (const float*)d_in[o + 14];
    p.W2   = (const float*)d_in[o + 15]; p.b2   = (const float*)d_in[o + 16];
    p.W3   = (const float*)d_in[o + 17]; p.b3   = (const float*)d_in[o + 18];
    p.W4   = (const float*)d_in[o + 19]; p.b4   = (const float*)d_in[o + 20];
    p.out  = (float*)d_out;

    cudaFuncSetAttribute(ggnn_main, cudaFuncAttributeMaxDynamicSharedMemorySize,
                         SMEM_FLOATS * (int)sizeof(float));

    ggnn_pre<<<TYPEC + 1, 192>>>(p);
    ggnn_main<<<Bc, 512, SMEM_FLOATS * (int)sizeof(float)>>>(p);
}

// round 2
// speedup vs baseline: 1.1330x; 1.1330x over previous
#include <cuda_runtime.h>
#include <cuda_bf16.h>
#include <math.h>

// Problem constants
#define Bc 128
#define Nc 128
#define Ec 64
#define TYPEC 201   // TYPE_NUM+1
#define RELC  51    // REL_NUM+1

#define BAR_B() asm volatile("bar.sync 1, 256;" ::: "memory")

// Precomputed batch-independent tables
__device__ float g_typeproj[TYPEC * 192];   // [tv][gate*64+e] = bg[e] + type_table[tv]@Wg[0:32]
__device__ float g_relproj[RELC * 64];      // [v][e]          = rel_table[v]@W_in[64:96]

struct GParams {
    const int*   node_slice;
    const int*   type_slice;
    const float* distance;
    const int*   rel_matrix;
    const int*   input_length;
    const float* emb_table;
    const float* type_table;
    const float* rel_table;
    const float* W_in; const float* b_in;
    const float* Wr;   const float* br;
    const float* Wz;   const float* bz;
    const float* Wt;   const float* bt;
    const float* W_co; const float* b_co;
    const float* W1;   const float* b1;
    const float* W2;   const float* b2;
    const float* W3;   const float* b3;
    const float* W4;   const float* b4;
    float* out;
};

// ---------------------------------------------------------------------------
// Kernel 0: batch-independent projection tables (tiny)
// ---------------------------------------------------------------------------
__global__ void ggnn_pre(GParams p) {
    int blk = blockIdx.x;
    int t = threadIdx.x;
    if (blk < TYPEC) {
        if (t < 192) {
            int gate = t >> 6, e = t & 63;
            const float* Wg = (gate == 0) ? p.Wr : ((gate == 1) ? p.Wz : p.Wt);
            const float* bg = (gate == 0) ? p.br : ((gate == 1) ? p.bz : p.bt);
            float acc = bg[e];
            #pragma unroll
            for (int k = 0; k < 32; k++)
                acc += p.type_table[blk * 32 + k] * Wg[k * 64 + e];
            g_typeproj[blk * 192 + t] = acc;
        }
    } else {
        if (t < 64) {
            for (int v = 0; v < RELC; v++) {
                float acc = 0.f;
                #pragma unroll
                for (int k = 0; k < 32; k++)
                    acc += p.rel_table[v * 32 + k] * p.W_in[(64 + k) * 64 + t];
                g_relproj[v * 64 + t] = acc;
            }
        }
    }
}

// ---------------------------------------------------------------------------
// Shared layout (float offsets)
// ---------------------------------------------------------------------------
#define SM_H     0        // 8192  : hidden@W_h + b_in (incrementally updated)
#define SM_HID   8192     // 8192  : hidden state
#define SM_NP    16384    // 24576 : now_part[i][gate*64+e]
#define SM_RP    40960    // 3264  : relproj copy
#define SM_DISC  44224    // 128
#define SM_PBUF  44352    // 2*9*64 = 1152 : double-buffered max partials (8 A-slots + 1 corr)
#define SM_DP    45504    // 64
#define SM_R     45568    // 64
#define SM_Z     45632    // 64
#define SM_HH    45696    // 64
#define SM_NR    45760    // 64
#define SM_BIN   45824    // 64
#define SM_RV    45888    // 3*128 ints : rel row ring
#define SM_TV    46272    // 128 ints
#define SM_FIN   46400    // 736
#define SM_STAGE 47136    // 8192 : init GEMM weight staging
#define SMEM_FLOATS 55328

__global__ void __launch_bounds__(512, 1) ggnn_main(GParams p) {
    extern __shared__ float S[];
    const int t = threadIdx.x;
    const int b = blockIdx.x;
    int* rvs = (int*)&S[SM_RV];
    int* tvs = (int*)&S[SM_TV];
    const int len = p.input_length[b];

    // ---------------- init gathers ----------------
    {
        const float4* emb4 = (const float4*)p.emb_table;
        float4* hid4 = (float4*)&S[SM_HID];
        for (int idx = t; idx < Nc * 16; idx += 512) {
            int j = idx >> 4, q = idx & 15;
            long long nd = p.node_slice[b * Nc + j];
            hid4[idx] = emb4[nd * 16 + q];
        }
    }
    if (t < 128) S[SM_DISC + t] = -0.1f * p.distance[b * Nc + t];
    if (t < 128) tvs[t] = p.type_slice[b * Nc + t];
    if (t < 128) rvs[t] = p.rel_matrix[((long long)b * Nc) * Nc + t];  // rel row 0 -> ring slot 0
    for (int idx = t; idx < RELC * 64; idx += 512) S[SM_RP + idx] = g_relproj[idx];
    if (t < 64) S[SM_BIN + t] = p.b_in[t];
    if (t >= 384 && t < 448) S[SM_PBUF + 8 * 64 + (t - 384)] = -1e30f;  // corr slot of buffer 0

    // ---------------- persistent gate weights in registers (group B only) ----
    float wRZ[32], wT[16], wH[16];
    if (t >= 256) {
        int u = t - 256;
        int ridx = u >> 1, half = u & 1;
        int gate = ridx >> 6, e_rz = ridx & 63;
        const float* src = gate ? p.Wz : p.Wr;
        #pragma unroll
        for (int k = 0; k < 32; k++) wRZ[k] = src[(96 + half * 32 + k) * 64 + e_rz];
        int e = u >> 2, q = u & 3;
        #pragma unroll
        for (int k = 0; k < 16; k++) {
            wT[k] = p.Wt[(96 + q * 16 + k) * 64 + e];
            wH[k] = p.W_in[(q * 16 + k) * 64 + e];
        }
    }
    __syncthreads();

    // ---------------- H init: H = hidden @ W_h + b_in ----------------
    for (int idx = t; idx < 4096; idx += 512) S[SM_STAGE + idx] = p.W_in[idx];
    __syncthreads();
    {
        int j0 = (t >> 4) << 2, e0 = (t & 15) << 2;
        float acc[4][4];
        #pragma unroll
        for (int m = 0; m < 4; m++)
            #pragma unroll
            for (int n = 0; n < 4; n++) acc[m][n] = S[SM_BIN + e0 + n];
        #pragma unroll 4
        for (int k = 0; k < 64; k++) {
            float4 w = *(const float4*)&S[SM_STAGE + k * 64 + e0];
            #pragma unroll
            for (int m = 0; m < 4; m++) {
                float h = S[SM_HID + (j0 + m) * 64 + k];
                acc[m][0] += h * w.x; acc[m][1] += h * w.y;
                acc[m][2] += h * w.z; acc[m][3] += h * w.w;
            }
        }
        #pragma unroll
        for (int m = 0; m < 4; m++)
            #pragma unroll
            for (int n = 0; n < 4; n++) S[SM_H + (j0 + m) * 64 + e0 + n] = acc[m][n];
    }
    __syncthreads();

    // ---------------- now_part: typeproj[tv] + node_emb @ Wg[32:96] ----------
    for (int idx = t; idx < 8192; idx += 512) {
        int k = idx >> 7, c = idx & 127;
        S[SM_STAGE + idx] = (c < 64) ? p.Wr[(32 + k) * 64 + c]
                                     : p.Wz[(32 + k) * 64 + (c - 64)];
    }
    __syncthreads();
    #pragma unroll
    for (int pss = 0; pss < 2; pss++) {
        int tid2 = t + pss * 512;
        int i0 = (tid2 >> 5) << 2, c0 = (tid2 & 31) << 2;
        float acc[4][4];
        #pragma unroll
        for (int m = 0; m < 4; m++) {
            const float* tp = &g_typeproj[tvs[i0 + m] * 192 + c0];
            acc[m][0] = tp[0]; acc[m][1] = tp[1]; acc[m][2] = tp[2]; acc[m][3] = tp[3];
        }
        #pragma unroll 4
        for (int k = 0; k < 64; k++) {
            float4 w = *(const float4*)&S[SM_STAGE + k * 128 + c0];
            #pragma unroll
            for (int m = 0; m < 4; m++) {
                float h = S[SM_HID + (i0 + m) * 64 + k];
                acc[m][0] += h * w.x; acc[m][1] += h * w.y;
                acc[m][2] += h * w.z; acc[m][3] += h * w.w;
            }
        }
        #pragma unroll
        for (int m = 0; m < 4; m++)
            #pragma unroll
            for (int n = 0; n < 4; n++)
                S[SM_NP + (i0 + m) * 192 + c0 + n] = acc[m][n];
    }
    __syncthreads();
    for (int idx = t; idx < 4096; idx += 512) {
        int k = idx >> 6, e = idx & 63;
        S[SM_STAGE + idx] = p.Wt[(32 + k) * 64 + e];
    }
    __syncthreads();
    {
        int i0 = (t >> 4) << 2, e0 = (t & 15) << 2;
        float acc[4][4];
        #pragma unroll
        for (int m = 0; m < 4; m++) {
            const float* tp = &g_typeproj[tvs[i0 + m] * 192 + 128 + e0];
            acc[m][0] = tp[0]; acc[m][1] = tp[1]; acc[m][2] = tp[2]; acc[m][3] = tp[3];
        }
        #pragma unroll 4
        for (int k = 0; k < 64; k++) {
            float4 w = *(const float4*)&S[SM_STAGE + k * 64 + e0];
            #pragma unroll
            for (int m = 0; m < 4; m++) {
                float h = S[SM_HID + (i0 + m) * 64 + k];
                acc[m][0] += h * w.x; acc[m][1] += h * w.y;
                acc[m][2] += h * w.z; acc[m][3] += h * w.w;
            }
        }
        #pragma unroll
        for (int m = 0; m < 4; m++)
            #pragma unroll
            for (int n = 0; n < 4; n++)
                S[SM_NP + (i0 + m) * 192 + 128 + e0 + n] = acc[m][n];
    }
    __syncthreads();

    // ---------------- pipelined scan ----------------
    // Iteration i: group A (t<256) computes masked-max partials for step i+1
    // over all rows j != i; group B (t>=256) runs the full gate chain of step i
    // and at iteration i+1 patches in the j==i correction before reducing.
    for (int i = -1; i < Nc; i++) {
        if (t < 256) {
            int rv_pref = 0;
            bool do_pref = (t < 128) && (i + 2 < Nc);
            if (do_pref)
                rv_pref = p.rel_matrix[((long long)b * Nc + (i + 2)) * Nc + t];
            if (i < Nc - 1) {
                const int s = i + 1;
                const int* rv = rvs + (s % 3) * 128;
                const int e4 = (t & 15) << 2;
                const int g = t >> 4;
                float a0 = -1e30f, a1 = -1e30f, a2 = -1e30f, a3 = -1e30f;
                #pragma unroll
                for (int jj = 0; jj < 8; jj++) {
                    int j = g + (jj << 4);
                    int rvj = rv[j];
                    bool valid = (rvj != 0) & (j < len) & (j != i);
                    float4 h  = *(const float4*)&S[SM_H + j * 64 + e4];
                    float4 rp = *(const float4*)&S[SM_RP + rvj * 64 + e4];
                    float d = S[SM_DISC + j];
                    float c0 = fmaxf(h.x + rp.x, 0.f) * d;
                    float c1 = fmaxf(h.y + rp.y, 0.f) * d;
                    float c2 = fmaxf(h.z + rp.z, 0.f) * d;
                    float c3 = fmaxf(h.w + rp.w, 0.f) * d;
                    if (valid) {
                        a0 = fmaxf(a0, c0); a1 = fmaxf(a1, c1);
                        a2 = fmaxf(a2, c2); a3 = fmaxf(a3, c3);
                    }
                }
                a0 = fmaxf(a0, __shfl_xor_sync(0xffffffffu, a0, 16));
                a1 = fmaxf(a1, __shfl_xor_sync(0xffffffffu, a1, 16));
                a2 = fmaxf(a2, __shfl_xor_sync(0xffffffffu, a2, 16));
                a3 = fmaxf(a3, __shfl_xor_sync(0xffffffffu, a3, 16));
                if ((t & 31) < 16) {
                    int w = t >> 5;
                    *(float4*)&S[SM_PBUF + ((s & 1) * 9 + w) * 64 + e4] =
                        make_float4(a0, a1, a2, a3);
                }
            }
            if (do_pref)
                rvs[((i + 2) % 3) * 128 + t] = rv_pref;
        } else if (i >= 0) {
            const int u = t - 256;
            // corr (j == i-1 for step i) + reduce -> dis_pre
            if (u < 64) {
                if (i > 0) {
                    int rvj = rvs[(i % 3) * 128 + (i - 1)];
                    float c = -1e30f;
                    if ((rvj != 0) && (i - 1 < len))
                        c = fmaxf(S[SM_H + (i - 1) * 64 + u] + S[SM_RP + rvj * 64 + u], 0.f)
                            * S[SM_DISC + (i - 1)];
                    S[SM_PBUF + ((i & 1) * 9 + 8) * 64 + u] = c;
                }
                float m = S[SM_PBUF + (i & 1) * 9 * 64 + u];
                #pragma unroll
                for (int s2 = 1; s2 < 9; s2++)
                    m = fmaxf(m, S[SM_PBUF + ((i & 1) * 9 + s2) * 64 + u]);
                S[SM_DP + u] = (m < -1e29f) ? 0.f : m;
            }
            BAR_B();
            // r, z gates: 2 threads per output, weights in regs
            {
                int ridx = u >> 1, half = u & 1;
                int gate = ridx >> 6, e = ridx & 63;
                const float4* dp4 = (const float4*)&S[SM_DP + half * 32];
                float s0 = 0.f, s1 = 0.f, s2 = 0.f, s3 = 0.f;
                #pragma unroll
                for (int c = 0; c < 8; c++) {
                    float4 d = dp4[c];
                    s0 += wRZ[c * 4 + 0] * d.x; s1 += wRZ[c * 4 + 1] * d.y;
                    s2 += wRZ[c * 4 + 2] * d.z; s3 += wRZ[c * 4 + 3] * d.w;
                }
                float sum = (s0 + s1) + (s2 + s3);
                sum += __shfl_xor_sync(0xffffffffu, sum, 1);
                if (half == 0) {
                    float v = S[SM_NP + i * 192 + gate * 64 + e] + sum;
                    S[(gate ? SM_Z : SM_R) + e] = 1.0f / (1.0f + __expf(-v));
                }
            }
            BAR_B();
            // h_hat: 4 threads per output
            {
                int e = u >> 2, q = u & 3;
                const float4* r4  = (const float4*)&S[SM_R + q * 16];
                const float4* dp4 = (const float4*)&S[SM_DP + q * 16];
                float s0 = 0.f, s1 = 0.f, s2 = 0.f, s3 = 0.f;
                #pragma unroll
                for (int c = 0; c < 4; c++) {
                    float4 r = r4[c]; float4 d = dp4[c];
                    s0 += wT[c * 4 + 0] * (r.x * d.x); s1 += wT[c * 4 + 1] * (r.y * d.y);
                    s2 += wT[c * 4 + 2] * (r.z * d.z); s3 += wT[c * 4 + 3] * (r.w * d.w);
                }
                float sum = (s0 + s1) + (s2 + s3);
                sum += __shfl_xor_sync(0xffffffffu, sum, 1);
                sum += __shfl_xor_sync(0xffffffffu, sum, 2);
                if (q == 0) {
                    float v = S[SM_NP + i * 192 + 128 + e] + sum;
                    float ex = __expf(2.f * v);
                    S[SM_HH + e] = 1.f - 2.f / (ex + 1.f);   // tanh, overflow-safe
                }
            }
            BAR_B();
            // GRU update -> new hidden row
            if (u < 64) {
                float z = S[SM_Z + u], dp = S[SM_DP + u], hh = S[SM_HH + u];
                float up = (1.0f - z) * dp + z * hh;
                float nr = (i < len) ? up : S[SM_HID + i * 64 + u];
                S[SM_HID + i * 64 + u] = nr;
                S[SM_NR + u] = nr;
            }
            BAR_B();
            // H row refresh: H[i] = b_in + new_row @ W_h
            {
                int e = u >> 2, q = u & 3;
                const float4* n4 = (const float4*)&S[SM_NR + q * 16];
                float s0 = 0.f, s1 = 0.f, s2 = 0.f, s3 = 0.f;
                #pragma unroll
                for (int c = 0; c < 4; c++) {
                    float4 n = n4[c];
                    s0 += wH[c * 4 + 0] * n.x; s1 += wH[c * 4 + 1] * n.y;
                    s2 += wH[c * 4 + 2] * n.z; s3 += wH[c * 4 + 3] * n.w;
                }
                float sum = (s0 + s1) + (s2 + s3);
                sum += __shfl_xor_sync(0xffffffffu, sum, 1);
                sum += __shfl_xor_sync(0xffffffffu, sum, 2);
                if (q == 0) S[SM_H + i * 64 + e] = S[SM_BIN + e] + sum;
            }
        }
        __syncthreads();
    }

    // ---------------- final head ----------------
    const int tE = t & 63, tJG = t >> 6;
    {
        float acc = -1e30f;
        #pragma unroll
        for (int jj = 0; jj < 16; jj++) {
            int j = tJG + (jj << 3);
            if (j < len) acc = fmaxf(acc, S[SM_HID + j * 64 + tE]);
        }
        S[SM_PBUF + tJG * 64 + tE] = acc;
    }
    __syncthreads();
    if (t < 64) {
        float m = S[SM_PBUF + t];
        #pragma unroll
        for (int g = 1; g < 8; g++) m = fmaxf(m, S[SM_PBUF + g * 64 + t]);
        S[SM_FIN + 128 + t] = m;                               // sub
        S[SM_FIN + t]       = S[SM_HID + t];                   // user
        S[SM_FIN + 64 + t]  = S[SM_HID + (len - 1) * 64 + t];  // item
    }
    __syncthreads();
    if (t < 128) {  // ua / ia
        int which = t >> 6, e = t & 63;
        const float* first = which ? &S[SM_FIN + 64] : &S[SM_FIN];
        float acc = p.b_co[e];
        #pragma unroll 4
        for (int k = 0; k < 64; k++) acc += first[k] * p.W_co[k * 64 + e];
        #pragma unroll 4
        for (int k = 0; k < 64; k++) acc += S[SM_FIN + 128 + k] * p.W_co[(64 + k) * 64 + e];
        S[SM_FIN + 192 + which * 64 + e] = fmaxf(acc, 0.f);
    }
    __syncthreads();
    if (t < 192) {  // temp = [ua*user, sub, ia*item]
        float v;
        if (t < 64)       v = S[SM_FIN + 192 + t] * S[SM_FIN + t];
        else if (t < 128) v = S[SM_FIN + 128 + (t - 64)];
        else              v = S[SM_FIN + 256 + (t - 128)] * S[SM_FIN + 64 + (t - 128)];
        S[SM_FIN + 320 + t] = v;
    }
    __syncthreads();
    if (t < 128) {
        float acc = p.b1[t];
        #pragma unroll 4
        for (int k = 0; k < 192; k++) acc += S[SM_FIN + 320 + k] * p.W1[k * 128 + t];
        S[SM_FIN + 512 + t] = fmaxf(acc, 0.f);
    }
    __syncthreads();
    if (t < 64) {
        float acc = p.b2[t];
        #pragma unroll 4
        for (int k = 0; k < 128; k++) acc += S[SM_FIN + 512 + k] * p.W2[k * 64 + t];
        S[SM_FIN + 640 + t] = fmaxf(acc, 0.f);
    }
    __syncthreads();
    if (t < 32) {
        float acc = p.b3[t];
        #pragma unroll 4
        for (int k = 0; k < 64; k++) acc += S[SM_FIN + 640 + k] * p.W3[k * 32 + t];
        S[SM_FIN + 704 + t] = fmaxf(acc, 0.f);
    }
    __syncthreads();
    if (t == 0) {
        float acc = p.b4[0];
        #pragma unroll
        for (int k = 0; k < 32; k++) acc += S[SM_FIN + 704 + k] * p.W4[k];
        p.out[b] = 1.0f / (1.0f + __expf(-acc));
    }
}

// ---------------------------------------------------------------------------
extern "C" void kernel_launch(void* const* d_in, const int* in_sizes, int n_in,
                              void* d_out, int out_size) {
    GParams p;
    p.node_slice   = (const int*)d_in[0];
    p.type_slice   = (const int*)d_in[1];
    p.distance     = (const float*)d_in[2];
    p.rel_matrix   = (const int*)d_in[3];
    p.input_length = (const int*)d_in[4];
    int o = (n_in >= 27) ? 6 : 5;
    p.emb_table  = (const float*)d_in[o + 0];
    p.type_table = (const float*)d_in[o + 1];
    p.rel_table  = (const float*)d_in[o + 2];
    p.W_in = (const float*)d_in[o + 3];  p.b_in = (const float*)d_in[o + 4];
    p.Wr   = (const float*)d_in[o + 5];  p.br   = (const float*)d_in[o + 6];
    p.Wz   = (const float*)d_in[o + 7];  p.bz   = (const float*)d_in[o + 8];
    p.Wt   = (const float*)d_in[o + 9];  p.bt   = (const float*)d_in[o + 10];
    p.W_co = (const float*)d_in[o + 11]; p.b_co = (const float*)d_in[o + 12];
    p.W1   = (const float*)d_in[o + 13]; p.b1   = (const float*)d_in[o + 14];
    p.W2   = (const float*)d_in[o + 15]; p.b2   = (const float*)d_in[o + 16];
    p.W3   = (const float*)d_in[o + 17]; p.b3   = (const float*)d_in[o + 18];
    p.W4   = (const float*)d_in[o + 19]; p.b4   = (const float*)d_in[o + 20];
    p.out  = (float*)d_out;

    cudaFuncSetAttribute(ggnn_main, cudaFuncAttributeMaxDynamicSharedMemorySize,
                         SMEM_FLOATS * (int)sizeof(float));

    ggnn_pre<<<TYPEC + 1, 192>>>(p);
    ggnn_main<<<Bc, 512, SMEM_FLOATS * (int)sizeof(float)>>>(p);
}